// round 15
// baseline (speedup 1.0000x reference)
#include <cuda_runtime.h>
#include <cuda_bf16.h>
#include <math.h>
#include <stdint.h>

#define BB 8
#define C1 64
#define C2 128
#define HH 64
#define WW 64
#define H2 128
#define W2 128

#define R_ELEMS (BB*C1*H2*W2)   /* 8388608 */
#define MAP_ELEMS (BB*H2*W2)    /* 131072  */
#define XP_ELEMS (BB*C2*HH*WW)  /* 2097152 */

__device__ float g_dep[R_ELEMS];
__device__ float g_im[MAP_ELEMS];
__device__ float g_im1[MAP_ELEMS];
__device__ float g_inc[MAP_ELEMS];
__device__ float g_outmap[MAP_ELEMS];

// transposed packed dep_x: [bi][chunk 8][y 64][x 64][16 ci-perm], u32 = hi<<16|lo
__device__ __align__(16) unsigned int g_xt[XP_ELEMS];
// packed (bf16hi<<16 | bf16lo) tensors for the 3x3 chain
__device__ unsigned int g_gpk[R_ELEMS];    // cur_x * outmap packed
__device__ unsigned int g_t1p[R_ELEMS];
__device__ unsigned int g_r1p[R_ELEMS];
__device__ unsigned int g_r2p[R_ELEMS];

// transformed up-conv weights: [tap 49][oc 256][ci 128 perm] hi/lo
#define WQ_ELEMS (49 * 256 * 128)
__device__ __align__(16) unsigned short g_wh[WQ_ELEMS];
__device__ __align__(16) unsigned short g_wl[WQ_ELEMS];
// transformed 3x3 weights: 4 slots of [tap 9][oc 64][ci 64 perm] hi/lo
#define W3_ELEMS (9 * 64 * 64)
__device__ __align__(16) unsigned short g_w3h[4 * W3_ELEMS];
__device__ __align__(16) unsigned short g_w3l[4 * W3_ELEMS];

// ---------------- helpers ----------------
__device__ __forceinline__ void split_bf16(float x, unsigned short& h, unsigned short& l) {
    __nv_bfloat16 bh = __float2bfloat16(x);
    float fh = __bfloat162float(bh);
    __nv_bfloat16 bl = __float2bfloat16(x - fh);
    h = *reinterpret_cast<unsigned short*>(&bh);
    l = *reinterpret_cast<unsigned short*>(&bl);
}
__device__ __forceinline__ unsigned int packf(float x) {
    unsigned short h, l;
    split_bf16(x, h, l);
    return ((unsigned int)h << 16) | (unsigned int)l;
}
__device__ __forceinline__ void mma16816(float* d,
    uint32_t a0, uint32_t a1, uint32_t a2, uint32_t a3,
    uint32_t b0, uint32_t b1)
{
    asm volatile(
        "mma.sync.aligned.m16n8k16.row.col.f32.bf16.bf16.f32 "
        "{%0,%1,%2,%3}, {%4,%5,%6,%7}, {%8,%9}, {%0,%1,%2,%3};"
        : "+f"(d[0]), "+f"(d[1]), "+f"(d[2]), "+f"(d[3])
        : "r"(a0), "r"(a1), "r"(a2), "r"(a3), "r"(b0), "r"(b1));
}
__device__ __forceinline__ uint32_t prmt(uint32_t a, uint32_t b, uint32_t s) {
    uint32_t r; asm("prmt.b32 %0, %1, %2, %3;" : "=r"(r) : "r"(a), "r"(b), "r"(s)); return r;
}
__device__ __forceinline__ uint32_t smem_u32(const void* p) {
    uint32_t a;
    asm("{ .reg .u64 t; cvta.to.shared.u64 t, %1; cvt.u32.u64 %0, t; }" : "=r"(a) : "l"(p));
    return a;
}
__device__ __forceinline__ void cp_async16(uint32_t saddr, const void* gptr, bool valid) {
    int sz = valid ? 16 : 0;
    asm volatile("cp.async.cg.shared.global [%0], [%1], 16, %2;"
                 :: "r"(saddr), "l"(gptr), "r"(sz) : "memory");
}
__device__ __forceinline__ void cp_async4(uint32_t saddr, const void* gptr, bool valid) {
    int sz = valid ? 4 : 0;
    asm volatile("cp.async.ca.shared.global [%0], [%1], 4, %2;"
                 :: "r"(saddr), "l"(gptr), "r"(sz) : "memory");
}

// ---------------- weight prep ----------------
__global__ void prep_w_kernel(const float* __restrict__ w) {
    int idx = blockIdx.x * blockDim.x + threadIdx.x;
    if (idx >= WQ_ELEMS) return;
    int cix = idx & 127, oc = (idx >> 7) & 255, tap = idx >> 15;
    int p = cix & 15, chunk = cix >> 4;
    int ci = chunk * 16 + 2 * (p >> 2) + (p & 1) + 8 * ((p >> 1) & 1);
    float v = w[(oc * 128 + ci) * 49 + tap];
    unsigned short h, l;
    split_bf16(v, h, l);
    g_wh[idx] = h;
    g_wl[idx] = l;
}
__global__ void prep_w3_kernel(const float* __restrict__ w, int slot) {
    int idx = blockIdx.x * blockDim.x + threadIdx.x;
    if (idx >= W3_ELEMS) return;
    int cix = idx & 63, oc = (idx >> 6) & 63, tap = idx >> 12;
    int p = cix & 15, chunk = cix >> 4;
    int ci = chunk * 16 + 2 * (p >> 2) + (p & 1) + 8 * ((p >> 1) & 1);
    float v = w[(oc * 64 + ci) * 9 + tap];
    unsigned short h, l;
    split_bf16(v, h, l);
    g_w3h[slot * W3_ELEMS + idx] = h;
    g_w3l[slot * W3_ELEMS + idx] = l;
}

// ---------------- input pack kernels ----------------
__global__ void pack_dep_t_kernel(const float* __restrict__ x) {
    int i = blockIdx.x * blockDim.x + threadIdx.x;
    if (i >= XP_ELEMS) return;
    int p = i & 15;
    int px = (i >> 4) & 4095;
    int chunk = (i >> 16) & 7;
    int bi = i >> 19;
    int ci = chunk * 16 + 2 * (p >> 2) + (p & 1) + 8 * ((p >> 1) & 1);
    g_xt[i] = packf(x[((bi * C2 + ci) << 12) + px]);
}
__global__ void gate_pack_kernel(const float* __restrict__ x) {
    int i = blockIdx.x * blockDim.x + threadIdx.x;
    if (i >= R_ELEMS) return;
    int b = i >> 20;
    int px = i & 16383;
    g_gpk[i] = packf(x[i] * g_outmap[(b << 14) + px]);
}

// ---------------- up-conv via mma.sync bf16x3, cp.async double-buffered ----
__global__ __launch_bounds__(256) void up_mma_kernel(
    const float* __restrict__ bias, const float* __restrict__ bn)
{
    extern __shared__ __align__(16) unsigned int Xs[];   // 2 * 9216

    int tid = threadIdx.x, lane = tid & 31, wid = tid >> 5;
    int g = lane >> 2, t = lane & 3;
    int mblk = blockIdx.x;
    int ntile = blockIdx.y;
    int bi = ntile >> 5;
    int y0 = (ntile & 31) * 2;
    int wm = wid >> 2, wn = wid & 3;
    int wy = wn >> 1;
    int wx = (wn & 1) * 32;
    int ocb = mblk * 64 + wm * 32;

    uint32_t sX = smem_u32(Xs);
    const unsigned int* gxb = g_xt + ((size_t)bi << 19);

    float acc[2][4][4];
    #pragma unroll
    for (int mf = 0; mf < 2; mf++)
        #pragma unroll
        for (int nf = 0; nf < 4; nf++)
            #pragma unroll
            for (int e = 0; e < 4; e++) acc[mf][nf][e] = 0.0f;

    #define UP_PREFETCH(ch, buf) do {                                          \
        const unsigned int* gc = gxb + ((ch) << 16);                           \
        _Pragma("unroll")                                                      \
        for (int i9 = 0; i9 < 9; i9++) {                                       \
            int u = tid + i9 * 256;                                            \
            int pq = u & 3;                                                    \
            int cc = (u >> 2) % 72;                                            \
            int rr = (u >> 2) / 72;                                            \
            int gy = y0 - 3 + rr, gx = cc - 3;                                 \
            bool vv = (gy >= 0 && gy < 64 && gx >= 0 && gx < 64);              \
            const unsigned int* src = gc +                                     \
                (vv ? ((((gy << 6) + gx) << 4) + (pq << 2)) : 0);              \
            cp_async16(sX + (((buf) * 9216 + u * 4) << 2), src, vv);           \
        }                                                                      \
        asm volatile("cp.async.commit_group;" ::: "memory");                   \
    } while (0)

    UP_PREFETCH(0, 0);
    #pragma unroll 1
    for (int chunk = 0; chunk < 8; chunk++) {
        if (chunk + 1 < 8) {
            UP_PREFETCH(chunk + 1, (chunk + 1) & 1);
            asm volatile("cp.async.wait_group 1;" ::: "memory");
        } else {
            asm volatile("cp.async.wait_group 0;" ::: "memory");
        }
        __syncthreads();
        const unsigned int* Xb = Xs + (chunk & 1) * 9216;

        for (int kh = 0; kh < 7; kh++) {
            #pragma unroll
            for (int kw = 0; kw < 7; kw++) {
                int tap = kh * 7 + kw;
                size_t aoff = ((size_t)(tap * 256 + ocb + g) << 7) + chunk * 16 + t * 4;
                uint2 ah00 = *(const uint2*)(g_wh + aoff);
                uint2 ah01 = *(const uint2*)(g_wh + aoff + (8 << 7));
                uint2 ah10 = *(const uint2*)(g_wh + aoff + (16 << 7));
                uint2 ah11 = *(const uint2*)(g_wh + aoff + (24 << 7));
                uint2 al00 = *(const uint2*)(g_wl + aoff);
                uint2 al01 = *(const uint2*)(g_wl + aoff + (8 << 7));
                uint2 al10 = *(const uint2*)(g_wl + aoff + (16 << 7));
                uint2 al11 = *(const uint2*)(g_wl + aoff + (24 << 7));
                int brow = wy + kh;
                int bcol = wx + kw + g;
                #pragma unroll
                for (int nf = 0; nf < 4; nf++) {
                    int spos = (brow * 72 + bcol + nf * 8) * 16 + t * 4;
                    uint4 q = *(const uint4*)(Xb + spos);
                    uint2 bh, bl;
                    bh.x = prmt(q.x, q.y, 0x7632);
                    bh.y = prmt(q.z, q.w, 0x7632);
                    bl.x = prmt(q.x, q.y, 0x5410);
                    bl.y = prmt(q.z, q.w, 0x5410);
                    mma16816(acc[0][nf], ah00.x, ah01.x, ah00.y, ah01.y, bh.x, bh.y);
                    mma16816(acc[1][nf], ah10.x, ah11.x, ah10.y, ah11.y, bh.x, bh.y);
                    mma16816(acc[0][nf], al00.x, al01.x, al00.y, al01.y, bh.x, bh.y);
                    mma16816(acc[1][nf], al10.x, al11.x, al10.y, al11.y, bh.x, bh.y);
                    mma16816(acc[0][nf], ah00.x, ah01.x, ah00.y, ah01.y, bl.x, bl.y);
                    mma16816(acc[1][nf], ah10.x, ah11.x, ah10.y, ah11.y, bl.x, bl.y);
                }
            }
        }
        __syncthreads();
    }

    int yy = y0 + wy;
    #pragma unroll
    for (int mf = 0; mf < 2; mf++) {
        #pragma unroll
        for (int half = 0; half < 2; half++) {
            int oc = ocb + mf * 16 + g + half * 8;
            float scale = bn[oc] * rsqrtf(bn[768 + oc] + 1e-5f);
            float off = (bias[oc] - bn[512 + oc]) * scale + bn[256 + oc];
            int c = oc >> 2, a = (oc >> 1) & 1, d = oc & 1;
            size_t rowb = ((size_t)(bi * C1 + c) * H2 + 2 * yy + a) * W2 + d;
            #pragma unroll
            for (int nf = 0; nf < 4; nf++) {
                #pragma unroll
                for (int e = 0; e < 2; e++) {
                    float v = acc[mf][nf][half * 2 + e];
                    int col = wx + nf * 8 + 2 * t + e;
                    g_dep[rowb + 2 * col] = fmaxf(fmaf(v, scale, off), 0.0f);
                }
            }
        }
    }
}

// ---------------- 3x3 convs via mma.sync bf16x3, cp.async double-buffered ----
// CTA: 64 oc x 128 px (one image row). grid = 1024 (bi*128 + y0).
// X tile: 3 rows x 132 cols x 16 ci packed u32 = 6336 u32/buffer, 2 buffers.
template<int MODE>
__global__ __launch_bounds__(256) void conv3_mma_kernel(
    const unsigned int* __restrict__ in, int wslot,
    const float* __restrict__ bias, const float* __restrict__ bnp,
    void* __restrict__ outp)
{
    extern __shared__ __align__(16) unsigned int Xs[];   // 2 * 6336

    int tid = threadIdx.x, lane = tid & 31, wid = tid >> 5;
    int g = lane >> 2, t = lane & 3;
    int blk = blockIdx.x;
    int bi = blk >> 7;
    int y0 = blk & 127;
    int wm = wid >> 2, wn = wid & 3;
    int wx = wn * 32;
    int ocb = wm * 32;

    uint32_t sX = smem_u32(Xs);
    const unsigned short* wh = g_w3h + wslot * W3_ELEMS;
    const unsigned short* wl = g_w3l + wslot * W3_ELEMS;

    float acc[2][4][4];
    #pragma unroll
    for (int mf = 0; mf < 2; mf++)
        #pragma unroll
        for (int nf = 0; nf < 4; nf++)
            #pragma unroll
            for (int e = 0; e < 4; e++) acc[mf][nf][e] = 0.0f;

    #define C3_PREFETCH(ch, buf) do {                                          \
        _Pragma("unroll")                                                      \
        for (int it = 0; it < 25; it++) {                                      \
            int idx = tid + it * 256;                                          \
            if (idx < 6336) {                                                  \
                int p = idx & 15;                                              \
                int cc = (idx >> 4) % 132;                                     \
                int r = (idx >> 4) / 132;                                      \
                int ci = (ch) * 16 + 2 * (p >> 2) + (p & 1) + 8 * ((p >> 1) & 1); \
                int gy = y0 - 1 + r, gx = cc - 1;                              \
                bool vv = (gy >= 0 && gy < H2 && gx >= 0 && gx < W2);          \
                const unsigned int* src = in +                                 \
                    (vv ? (((size_t)(bi * C1 + ci) << 14) + (gy << 7) + gx) : 0); \
                cp_async4(sX + (((buf) * 6336 + idx) << 2), src, vv);          \
            }                                                                  \
        }                                                                      \
        asm volatile("cp.async.commit_group;" ::: "memory");                   \
    } while (0)

    C3_PREFETCH(0, 0);
    #pragma unroll 1
    for (int chunk = 0; chunk < 4; chunk++) {
        if (chunk + 1 < 4) {
            C3_PREFETCH(chunk + 1, (chunk + 1) & 1);
            asm volatile("cp.async.wait_group 1;" ::: "memory");
        } else {
            asm volatile("cp.async.wait_group 0;" ::: "memory");
        }
        __syncthreads();
        const unsigned int* Xb = Xs + (chunk & 1) * 6336;

        #pragma unroll
        for (int kh = 0; kh < 3; kh++) {
            #pragma unroll
            for (int kw = 0; kw < 3; kw++) {
                int tap = kh * 3 + kw;
                int aoff = ((tap * 64 + ocb + g) << 6) + chunk * 16 + t * 4;
                uint2 ah00 = *(const uint2*)(wh + aoff);
                uint2 ah01 = *(const uint2*)(wh + aoff + (8 << 6));
                uint2 ah10 = *(const uint2*)(wh + aoff + (16 << 6));
                uint2 ah11 = *(const uint2*)(wh + aoff + (24 << 6));
                uint2 al00 = *(const uint2*)(wl + aoff);
                uint2 al01 = *(const uint2*)(wl + aoff + (8 << 6));
                uint2 al10 = *(const uint2*)(wl + aoff + (16 << 6));
                uint2 al11 = *(const uint2*)(wl + aoff + (24 << 6));
                int bcol = wx + kw + g;
                #pragma unroll
                for (int nf = 0; nf < 4; nf++) {
                    int spos = ((kh * 132 + bcol + nf * 8) << 4) + t * 4;
                    uint4 q = *(const uint4*)(Xb + spos);
                    uint2 bh, bl;
                    bh.x = prmt(q.x, q.y, 0x7632);
                    bh.y = prmt(q.z, q.w, 0x7632);
                    bl.x = prmt(q.x, q.y, 0x5410);
                    bl.y = prmt(q.z, q.w, 0x5410);
                    mma16816(acc[0][nf], ah00.x, ah01.x, ah00.y, ah01.y, bh.x, bh.y);
                    mma16816(acc[1][nf], ah10.x, ah11.x, ah10.y, ah11.y, bh.x, bh.y);
                    mma16816(acc[0][nf], al00.x, al01.x, al00.y, al01.y, bh.x, bh.y);
                    mma16816(acc[1][nf], al10.x, al11.x, al10.y, al11.y, bh.x, bh.y);
                    mma16816(acc[0][nf], ah00.x, ah01.x, ah00.y, ah01.y, bl.x, bl.y);
                    mma16816(acc[1][nf], ah10.x, ah11.x, ah10.y, ah11.y, bl.x, bl.y);
                }
            }
        }
        __syncthreads();
    }

    #pragma unroll
    for (int mf = 0; mf < 2; mf++) {
        #pragma unroll
        for (int half = 0; half < 2; half++) {
            int oc = ocb + mf * 16 + g + half * 8;
            size_t rowb = ((size_t)(bi * C1 + oc) << 14) + (y0 << 7);
            if (MODE == 0) {
                float bt = bnp[0];
                float bz = bias[oc];
                unsigned int* po = (unsigned int*)outp;
                #pragma unroll
                for (int nf = 0; nf < 4; nf++)
                    #pragma unroll
                    for (int e = 0; e < 2; e++) {
                        int col = wx + nf * 8 + 2 * t + e;
                        float v = g_dep[rowb + col]
                                + bt * (acc[mf][nf][half * 2 + e] + bz);
                        po[rowb + col] = packf(v);
                    }
            } else {
                float scale = bnp[oc] * rsqrtf(bnp[192 + oc] + 1e-5f);
                float off = (bias[oc] - bnp[128 + oc]) * scale + bnp[64 + oc];
                #pragma unroll
                for (int nf = 0; nf < 4; nf++)
                    #pragma unroll
                    for (int e = 0; e < 2; e++) {
                        int col = wx + nf * 8 + 2 * t + e;
                        float v = acc[mf][nf][half * 2 + e];
                        v = fmaxf(fmaf(v, scale, off), 0.0f);
                        if (MODE == 1) ((unsigned int*)outp)[rowb + col] = packf(v);
                        else           ((float*)outp)[rowb + col] = v;
                    }
            }
        }
    }
}

// ---------------------------------------------------------------------------
// map pipeline
// ---------------------------------------------------------------------------
__global__ void upsample_sig_kernel(const float* __restrict__ in_map) {
    int idx = blockIdx.x * blockDim.x + threadIdx.x;
    if (idx >= MAP_ELEMS) return;
    int b = idx / (H2 * W2), p = idx % (H2 * W2);
    int oy = p / W2, ox = p % W2;
    float cy = oy * (63.0f / 127.0f), cx = ox * (63.0f / 127.0f);
    int y0 = (int)floorf(cy); int y1 = min(y0 + 1, HH - 1);
    int x0 = (int)floorf(cx); int x1 = min(x0 + 1, WW - 1);
    float wy = cy - y0, wx = cx - x0;
    const float* m = in_map + b * HH * WW;
    float u = m[y0 * WW + x0] * (1.f - wy) * (1.f - wx) + m[y0 * WW + x1] * (1.f - wy) * wx
            + m[y1 * WW + x0] * wy * (1.f - wx)         + m[y1 * WW + x1] * wy * wx;
    g_im[idx]  = 1.0f / (1.0f + expf(-u));
    g_im1[idx] = 1.0f / (1.0f + expf(-(1.0f - u)));
}

__device__ __forceinline__ float max3x3(const float* m, int oy, int ox) {
    float mx = -3.4e38f;
    #pragma unroll
    for (int dy = -1; dy <= 1; dy++) {
        int y = oy + dy;
        if (y < 0 || y >= H2) continue;
        #pragma unroll
        for (int dx = -1; dx <= 1; dx++) {
            int x = ox + dx;
            if (x < 0 || x >= W2) continue;
            mx = fmaxf(mx, m[y * W2 + x]);
        }
    }
    return mx;
}

__global__ void inc_kernel() {
    int idx = blockIdx.x * blockDim.x + threadIdx.x;
    if (idx >= MAP_ELEMS) return;
    int b = idx / (H2 * W2), p = idx % (H2 * W2);
    const float* m = g_im + b * H2 * W2;
    g_inc[idx] = max3x3(m, p / W2, p % W2) - m[p];
}

__global__ void outmap_kernel() {
    int idx = blockIdx.x * blockDim.x + threadIdx.x;
    if (idx >= MAP_ELEMS) return;
    int b = idx / (H2 * W2), p = idx % (H2 * W2);
    const float* mi = g_inc + b * H2 * W2;
    const float* m1 = g_im1 + b * H2 * W2;
    g_outmap[idx] = max3x3(mi, p / W2, p % W2) + max3x3(m1, p / W2, p % W2) - m1[p];
}

// ---------------------------------------------------------------------------
// out-conv 7x7 (64->1)
// ---------------------------------------------------------------------------
__global__ __launch_bounds__(256) void out_conv_kernel(
    const float* __restrict__ rin, const float* __restrict__ w,
    const float* __restrict__ bias, float* __restrict__ out)
{
    __shared__ float sIn[22 * 22];
    __shared__ float sW[49];
    int tid = threadIdx.x, tx = tid & 15, ty = tid >> 4;
    int bx = blockIdx.x, by = blockIdx.y, b = blockIdx.z;
    int y0 = by * 16 - 3, x0 = bx * 16 - 3;

    float acc = 0.0f;
    for (int ci = 0; ci < C1; ci++) {
        const float* xin = rin + (b * C1 + ci) * H2 * W2;
        for (int i = tid; i < 22 * 22; i += 256) {
            int r = i / 22, c = i % 22, gy = y0 + r, gx = x0 + c;
            sIn[i] = (gy >= 0 && gy < H2 && gx >= 0 && gx < W2) ? xin[gy * W2 + gx] : 0.0f;
        }
        if (tid < 49) sW[tid] = w[ci * 49 + tid];
        __syncthreads();
        #pragma unroll 1
        for (int kh = 0; kh < 7; kh++)
            #pragma unroll
            for (int kw = 0; kw < 7; kw++)
                acc = fmaf(sIn[(ty + kh) * 22 + (tx + kw)], sW[kh * 7 + kw], acc);
        __syncthreads();
    }
    out[b * H2 * W2 + (by * 16 + ty) * W2 + bx * 16 + tx] = acc + bias[0];
}

// ---------------------------------------------------------------------------
extern "C" void kernel_launch(void* const* d_in, const int* in_sizes, int n_in,
                              void* d_out, int out_size) {
    const float* cur_x   = (const float*)d_in[0];
    const float* dep_x   = (const float*)d_in[1];
    const float* in_map  = (const float*)d_in[2];
    const float* up_w    = (const float*)d_in[3];
    const float* up_b    = (const float*)d_in[4];
    const float* up_bn   = (const float*)d_in[5];
    const float* conv2_w = (const float*)d_in[6];
    const float* conv2_b = (const float*)d_in[7];
    const float* d1_w    = (const float*)d_in[8];
    const float* d1_b    = (const float*)d_in[9];
    const float* d1_bn   = (const float*)d_in[10];
    const float* d2_w    = (const float*)d_in[11];
    const float* d2_b    = (const float*)d_in[12];
    const float* d2_bn   = (const float*)d_in[13];
    const float* d3_w    = (const float*)d_in[14];
    const float* d3_b    = (const float*)d_in[15];
    const float* d3_bn   = (const float*)d_in[16];
    const float* out_w   = (const float*)d_in[17];
    const float* out_b   = (const float*)d_in[18];
    const float* beta    = (const float*)d_in[19];
    float* out = (float*)d_out;

    unsigned int *p_gpk, *p_t1p, *p_r1p, *p_r2p;
    cudaGetSymbolAddress((void**)&p_gpk, g_gpk);
    cudaGetSymbolAddress((void**)&p_t1p, g_t1p);
    cudaGetSymbolAddress((void**)&p_r1p, g_r1p);
    cudaGetSymbolAddress((void**)&p_r2p, g_r2p);

    const int UP_SMEM = 2 * 9216 * 4;   // 73728 B
    const int C3_SMEM = 2 * 6336 * 4;   // 50688 B
    cudaFuncSetAttribute(up_mma_kernel, cudaFuncAttributeMaxDynamicSharedMemorySize, UP_SMEM);
    cudaFuncSetAttribute(conv3_mma_kernel<0>, cudaFuncAttributeMaxDynamicSharedMemorySize, C3_SMEM);
    cudaFuncSetAttribute(conv3_mma_kernel<1>, cudaFuncAttributeMaxDynamicSharedMemorySize, C3_SMEM);
    cudaFuncSetAttribute(conv3_mma_kernel<2>, cudaFuncAttributeMaxDynamicSharedMemorySize, C3_SMEM);

    prep_w_kernel<<<(WQ_ELEMS + 255) / 256, 256>>>(up_w);
    prep_w3_kernel<<<(W3_ELEMS + 255) / 256, 256>>>(conv2_w, 0);
    prep_w3_kernel<<<(W3_ELEMS + 255) / 256, 256>>>(d1_w, 1);
    prep_w3_kernel<<<(W3_ELEMS + 255) / 256, 256>>>(d2_w, 2);
    prep_w3_kernel<<<(W3_ELEMS + 255) / 256, 256>>>(d3_w, 3);
    pack_dep_t_kernel<<<(XP_ELEMS + 255) / 256, 256>>>(dep_x);

    upsample_sig_kernel<<<MAP_ELEMS / 256, 256>>>(in_map);
    inc_kernel<<<MAP_ELEMS / 256, 256>>>();
    outmap_kernel<<<MAP_ELEMS / 256, 256>>>();
    gate_pack_kernel<<<(R_ELEMS + 255) / 256, 256>>>(cur_x);

    up_mma_kernel<<<dim3(4, 256), 256, UP_SMEM>>>(up_b, up_bn);

    conv3_mma_kernel<0><<<1024, 256, C3_SMEM>>>(p_gpk, 0, conv2_b, beta, p_t1p);
    conv3_mma_kernel<1><<<1024, 256, C3_SMEM>>>(p_t1p, 1, d1_b, d1_bn, p_r1p);
    conv3_mma_kernel<1><<<1024, 256, C3_SMEM>>>(p_r1p, 2, d2_b, d2_bn, p_r2p);
    conv3_mma_kernel<2><<<1024, 256, C3_SMEM>>>(p_r2p, 3, d3_b, d3_bn, out);

    out_conv_kernel<<<dim3(8, 8, 8), 256>>>(out, out_w, out_b, out + R_ELEMS);
}

// round 16
// speedup vs baseline: 1.0578x; 1.0578x over previous
#include <cuda_runtime.h>
#include <cuda_bf16.h>
#include <math.h>
#include <stdint.h>

#define BB 8
#define C1 64
#define C2 128
#define HH 64
#define WW 64
#define H2 128
#define W2 128

#define R_ELEMS (BB*C1*H2*W2)   /* 8388608 */
#define MAP_ELEMS (BB*H2*W2)    /* 131072  */
#define XP_ELEMS (BB*C2*HH*WW)  /* 2097152 */

__device__ float g_dep[R_ELEMS];
__device__ float g_im[MAP_ELEMS];
__device__ float g_im1[MAP_ELEMS];
__device__ float g_inc[MAP_ELEMS];
__device__ float g_outmap[MAP_ELEMS];

// transposed packed dep_x: [bi][chunk 8][y 64][x 64][16 ci-perm], u32 = hi<<16|lo
__device__ __align__(16) unsigned int g_xt[XP_ELEMS];
// packed (bf16hi<<16 | bf16lo) tensors for the 3x3 chain
__device__ unsigned int g_gpk[R_ELEMS];    // cur_x * outmap packed
__device__ unsigned int g_t1p[R_ELEMS];
__device__ unsigned int g_r1p[R_ELEMS];
__device__ unsigned int g_r2p[R_ELEMS];

// transformed up-conv weights: [tap 49][oc 256][ci 128 perm] hi/lo
#define WQ_ELEMS (49 * 256 * 128)
__device__ __align__(16) unsigned short g_wh[WQ_ELEMS];
__device__ __align__(16) unsigned short g_wl[WQ_ELEMS];
// transformed 3x3 weights: 4 slots of [tap 9][oc 64][ci 64 perm] hi/lo
#define W3_ELEMS (9 * 64 * 64)
__device__ __align__(16) unsigned short g_w3h[4 * W3_ELEMS];
__device__ __align__(16) unsigned short g_w3l[4 * W3_ELEMS];

// ---------------- helpers ----------------
__device__ __forceinline__ void split_bf16(float x, unsigned short& h, unsigned short& l) {
    __nv_bfloat16 bh = __float2bfloat16(x);
    float fh = __bfloat162float(bh);
    __nv_bfloat16 bl = __float2bfloat16(x - fh);
    h = *reinterpret_cast<unsigned short*>(&bh);
    l = *reinterpret_cast<unsigned short*>(&bl);
}
__device__ __forceinline__ unsigned int packf(float x) {
    unsigned short h, l;
    split_bf16(x, h, l);
    return ((unsigned int)h << 16) | (unsigned int)l;
}
__device__ __forceinline__ void mma16816(float* d,
    uint32_t a0, uint32_t a1, uint32_t a2, uint32_t a3,
    uint32_t b0, uint32_t b1)
{
    asm volatile(
        "mma.sync.aligned.m16n8k16.row.col.f32.bf16.bf16.f32 "
        "{%0,%1,%2,%3}, {%4,%5,%6,%7}, {%8,%9}, {%0,%1,%2,%3};"
        : "+f"(d[0]), "+f"(d[1]), "+f"(d[2]), "+f"(d[3])
        : "r"(a0), "r"(a1), "r"(a2), "r"(a3), "r"(b0), "r"(b1));
}
__device__ __forceinline__ uint32_t prmt(uint32_t a, uint32_t b, uint32_t s) {
    uint32_t r; asm("prmt.b32 %0, %1, %2, %3;" : "=r"(r) : "r"(a), "r"(b), "r"(s)); return r;
}
__device__ __forceinline__ uint32_t smem_u32(const void* p) {
    uint32_t a;
    asm("{ .reg .u64 t; cvta.to.shared.u64 t, %1; cvt.u32.u64 %0, t; }" : "=r"(a) : "l"(p));
    return a;
}
__device__ __forceinline__ void cp_async16(uint32_t saddr, const void* gptr, bool valid) {
    int sz = valid ? 16 : 0;
    asm volatile("cp.async.cg.shared.global [%0], [%1], 16, %2;"
                 :: "r"(saddr), "l"(gptr), "r"(sz) : "memory");
}
__device__ __forceinline__ uint64_t f2pk(float lo, float hi) {
    uint64_t r;
    asm("mov.b64 %0, {%1, %2};" : "=l"(r) : "f"(lo), "f"(hi));
    return r;
}
__device__ __forceinline__ void ffma2(uint64_t& d, uint64_t a, uint64_t b) {
    asm("fma.rn.f32x2 %0, %1, %2, %0;" : "+l"(d) : "l"(a), "l"(b));
}
__device__ __forceinline__ float2 f2un(uint64_t v) {
    float2 r;
    asm("mov.b64 {%0, %1}, %2;" : "=f"(r.x), "=f"(r.y) : "l"(v));
    return r;
}

// ---------------- weight prep ----------------
__global__ void prep_w_kernel(const float* __restrict__ w) {
    int idx = blockIdx.x * blockDim.x + threadIdx.x;
    if (idx >= WQ_ELEMS) return;
    int cix = idx & 127, oc = (idx >> 7) & 255, tap = idx >> 15;
    int p = cix & 15, chunk = cix >> 4;
    int ci = chunk * 16 + 2 * (p >> 2) + (p & 1) + 8 * ((p >> 1) & 1);
    float v = w[(oc * 128 + ci) * 49 + tap];
    unsigned short h, l;
    split_bf16(v, h, l);
    g_wh[idx] = h;
    g_wl[idx] = l;
}
// all 4 slots in one launch: grid.y = slot
__global__ void prep_w3_all_kernel(const float* __restrict__ w0,
                                   const float* __restrict__ w1,
                                   const float* __restrict__ w2,
                                   const float* __restrict__ w3) {
    int idx = blockIdx.x * blockDim.x + threadIdx.x;
    if (idx >= W3_ELEMS) return;
    int slot = blockIdx.y;
    const float* w = (slot == 0) ? w0 : (slot == 1) ? w1 : (slot == 2) ? w2 : w3;
    int cix = idx & 63, oc = (idx >> 6) & 63, tap = idx >> 12;
    int p = cix & 15, chunk = cix >> 4;
    int ci = chunk * 16 + 2 * (p >> 2) + (p & 1) + 8 * ((p >> 1) & 1);
    float v = w[(oc * 64 + ci) * 9 + tap];
    unsigned short h, l;
    split_bf16(v, h, l);
    g_w3h[slot * W3_ELEMS + idx] = h;
    g_w3l[slot * W3_ELEMS + idx] = l;
}

// ---------------- input pack kernels ----------------
__global__ void pack_dep_t_kernel(const float* __restrict__ x) {
    int i = blockIdx.x * blockDim.x + threadIdx.x;
    if (i >= XP_ELEMS) return;
    int p = i & 15;
    int px = (i >> 4) & 4095;
    int chunk = (i >> 16) & 7;
    int bi = i >> 19;
    int ci = chunk * 16 + 2 * (p >> 2) + (p & 1) + 8 * ((p >> 1) & 1);
    g_xt[i] = packf(x[((bi * C2 + ci) << 12) + px]);
}
__global__ void gate_pack_kernel(const float* __restrict__ x) {
    int i = blockIdx.x * blockDim.x + threadIdx.x;
    if (i >= R_ELEMS) return;
    int b = i >> 20;
    int px = i & 16383;
    g_gpk[i] = packf(x[i] * g_outmap[(b << 14) + px]);
}

// ---------------- up-conv via mma.sync bf16x3, cp.async double-buffered ----
__global__ __launch_bounds__(256) void up_mma_kernel(
    const float* __restrict__ bias, const float* __restrict__ bn)
{
    extern __shared__ __align__(16) unsigned int Xs[];   // 2 * 9216

    int tid = threadIdx.x, lane = tid & 31, wid = tid >> 5;
    int g = lane >> 2, t = lane & 3;
    int mblk = blockIdx.x;
    int ntile = blockIdx.y;
    int bi = ntile >> 5;
    int y0 = (ntile & 31) * 2;
    int wm = wid >> 2, wn = wid & 3;
    int wy = wn >> 1;
    int wx = (wn & 1) * 32;
    int ocb = mblk * 64 + wm * 32;

    uint32_t sX = smem_u32(Xs);
    const unsigned int* gxb = g_xt + ((size_t)bi << 19);

    float acc[2][4][4];
    #pragma unroll
    for (int mf = 0; mf < 2; mf++)
        #pragma unroll
        for (int nf = 0; nf < 4; nf++)
            #pragma unroll
            for (int e = 0; e < 4; e++) acc[mf][nf][e] = 0.0f;

    #define UP_PREFETCH(ch, buf) do {                                          \
        const unsigned int* gc = gxb + ((ch) << 16);                           \
        _Pragma("unroll")                                                      \
        for (int i9 = 0; i9 < 9; i9++) {                                       \
            int u = tid + i9 * 256;                                            \
            int pq = u & 3;                                                    \
            int cc = (u >> 2) % 72;                                            \
            int rr = (u >> 2) / 72;                                            \
            int gy = y0 - 3 + rr, gx = cc - 3;                                 \
            bool vv = (gy >= 0 && gy < 64 && gx >= 0 && gx < 64);              \
            const unsigned int* src = gc +                                     \
                (vv ? ((((gy << 6) + gx) << 4) + (pq << 2)) : 0);              \
            cp_async16(sX + (((buf) * 9216 + u * 4) << 2), src, vv);           \
        }                                                                      \
        asm volatile("cp.async.commit_group;" ::: "memory");                   \
    } while (0)

    UP_PREFETCH(0, 0);
    #pragma unroll 1
    for (int chunk = 0; chunk < 8; chunk++) {
        if (chunk + 1 < 8) {
            UP_PREFETCH(chunk + 1, (chunk + 1) & 1);
            asm volatile("cp.async.wait_group 1;" ::: "memory");
        } else {
            asm volatile("cp.async.wait_group 0;" ::: "memory");
        }
        __syncthreads();
        const unsigned int* Xb = Xs + (chunk & 1) * 9216;

        for (int kh = 0; kh < 7; kh++) {
            #pragma unroll
            for (int kw = 0; kw < 7; kw++) {
                int tap = kh * 7 + kw;
                size_t aoff = ((size_t)(tap * 256 + ocb + g) << 7) + chunk * 16 + t * 4;
                uint2 ah00 = *(const uint2*)(g_wh + aoff);
                uint2 ah01 = *(const uint2*)(g_wh + aoff + (8 << 7));
                uint2 ah10 = *(const uint2*)(g_wh + aoff + (16 << 7));
                uint2 ah11 = *(const uint2*)(g_wh + aoff + (24 << 7));
                uint2 al00 = *(const uint2*)(g_wl + aoff);
                uint2 al01 = *(const uint2*)(g_wl + aoff + (8 << 7));
                uint2 al10 = *(const uint2*)(g_wl + aoff + (16 << 7));
                uint2 al11 = *(const uint2*)(g_wl + aoff + (24 << 7));
                int brow = wy + kh;
                int bcol = wx + kw + g;
                #pragma unroll
                for (int nf = 0; nf < 4; nf++) {
                    int spos = (brow * 72 + bcol + nf * 8) * 16 + t * 4;
                    uint4 q = *(const uint4*)(Xb + spos);
                    uint2 bh, bl;
                    bh.x = prmt(q.x, q.y, 0x7632);
                    bh.y = prmt(q.z, q.w, 0x7632);
                    bl.x = prmt(q.x, q.y, 0x5410);
                    bl.y = prmt(q.z, q.w, 0x5410);
                    mma16816(acc[0][nf], ah00.x, ah01.x, ah00.y, ah01.y, bh.x, bh.y);
                    mma16816(acc[1][nf], ah10.x, ah11.x, ah10.y, ah11.y, bh.x, bh.y);
                    mma16816(acc[0][nf], al00.x, al01.x, al00.y, al01.y, bh.x, bh.y);
                    mma16816(acc[1][nf], al10.x, al11.x, al10.y, al11.y, bh.x, bh.y);
                    mma16816(acc[0][nf], ah00.x, ah01.x, ah00.y, ah01.y, bl.x, bl.y);
                    mma16816(acc[1][nf], ah10.x, ah11.x, ah10.y, ah11.y, bl.x, bl.y);
                }
            }
        }
        __syncthreads();
    }

    int yy = y0 + wy;
    #pragma unroll
    for (int mf = 0; mf < 2; mf++) {
        #pragma unroll
        for (int half = 0; half < 2; half++) {
            int oc = ocb + mf * 16 + g + half * 8;
            float scale = bn[oc] * rsqrtf(bn[768 + oc] + 1e-5f);
            float off = (bias[oc] - bn[512 + oc]) * scale + bn[256 + oc];
            int c = oc >> 2, a = (oc >> 1) & 1, d = oc & 1;
            size_t rowb = ((size_t)(bi * C1 + c) * H2 + 2 * yy + a) * W2 + d;
            #pragma unroll
            for (int nf = 0; nf < 4; nf++) {
                #pragma unroll
                for (int e = 0; e < 2; e++) {
                    float v = acc[mf][nf][half * 2 + e];
                    int col = wx + nf * 8 + 2 * t + e;
                    g_dep[rowb + 2 * col] = fmaxf(fmaf(v, scale, off), 0.0f);
                }
            }
        }
    }
}

// ---------------- 3x3 convs via mma.sync bf16x3 (R14 proven version) --------
template<int MODE>
__global__ __launch_bounds__(256) void conv3_mma_kernel(
    const unsigned int* __restrict__ in, int wslot,
    const float* __restrict__ bias, const float* __restrict__ bnp,
    void* __restrict__ outp)
{
    __shared__ __align__(16) unsigned short Xh[3 * 132 * 16];
    __shared__ __align__(16) unsigned short Xl[3 * 132 * 16];

    int tid = threadIdx.x, lane = tid & 31, wid = tid >> 5;
    int g = lane >> 2, t = lane & 3;
    int blk = blockIdx.x;
    int bi = blk >> 7;
    int y0 = blk & 127;
    int wm = wid >> 2, wn = wid & 3;
    int wx = wn * 32;
    int ocb = wm * 32;

    const unsigned short* wh = g_w3h + wslot * W3_ELEMS;
    const unsigned short* wl = g_w3l + wslot * W3_ELEMS;

    float acc[2][4][4];
    #pragma unroll
    for (int mf = 0; mf < 2; mf++)
        #pragma unroll
        for (int nf = 0; nf < 4; nf++)
            #pragma unroll
            for (int e = 0; e < 4; e++) acc[mf][nf][e] = 0.0f;

    for (int chunk = 0; chunk < 4; chunk++) {
        __syncthreads();
        #pragma unroll 5
        for (int it = 0; it < 25; it++) {
            int idx = tid + it * 256;
            if (idx < 3 * 132 * 16) {
                int p = idx & 15;
                int cc = (idx >> 4) % 132;
                int r = (idx >> 4) / 132;
                int ci = chunk * 16 + 2 * (p >> 2) + (p & 1) + 8 * ((p >> 1) & 1);
                int gy = y0 - 1 + r, gx = cc - 1;
                unsigned int v = 0;
                if (gy >= 0 && gy < H2 && gx >= 0 && gx < W2)
                    v = in[((bi * C1 + ci) << 14) + (gy << 7) + gx];
                Xh[idx] = (unsigned short)(v >> 16);
                Xl[idx] = (unsigned short)v;
            }
        }
        __syncthreads();

        #pragma unroll
        for (int kh = 0; kh < 3; kh++) {
            #pragma unroll
            for (int kw = 0; kw < 3; kw++) {
                int tap = kh * 3 + kw;
                int aoff = ((tap * 64 + ocb + g) << 6) + chunk * 16 + t * 4;
                uint2 ah00 = *(const uint2*)(wh + aoff);
                uint2 ah01 = *(const uint2*)(wh + aoff + (8 << 6));
                uint2 ah10 = *(const uint2*)(wh + aoff + (16 << 6));
                uint2 ah11 = *(const uint2*)(wh + aoff + (24 << 6));
                uint2 al00 = *(const uint2*)(wl + aoff);
                uint2 al01 = *(const uint2*)(wl + aoff + (8 << 6));
                uint2 al10 = *(const uint2*)(wl + aoff + (16 << 6));
                uint2 al11 = *(const uint2*)(wl + aoff + (24 << 6));
                int bcol = wx + kw + g;
                #pragma unroll
                for (int nf = 0; nf < 4; nf++) {
                    int spos = ((kh * 132 + bcol + nf * 8) << 4) + t * 4;
                    uint2 bh = *(const uint2*)(Xh + spos);
                    uint2 bl = *(const uint2*)(Xl + spos);
                    mma16816(acc[0][nf], ah00.x, ah01.x, ah00.y, ah01.y, bh.x, bh.y);
                    mma16816(acc[1][nf], ah10.x, ah11.x, ah10.y, ah11.y, bh.x, bh.y);
                    mma16816(acc[0][nf], al00.x, al01.x, al00.y, al01.y, bh.x, bh.y);
                    mma16816(acc[1][nf], al10.x, al11.x, al10.y, al11.y, bh.x, bh.y);
                    mma16816(acc[0][nf], ah00.x, ah01.x, ah00.y, ah01.y, bl.x, bl.y);
                    mma16816(acc[1][nf], ah10.x, ah11.x, ah10.y, ah11.y, bl.x, bl.y);
                }
            }
        }
    }

    #pragma unroll
    for (int mf = 0; mf < 2; mf++) {
        #pragma unroll
        for (int half = 0; half < 2; half++) {
            int oc = ocb + mf * 16 + g + half * 8;
            size_t rowb = ((size_t)(bi * C1 + oc) << 14) + (y0 << 7);
            if (MODE == 0) {
                float bt = bnp[0];
                float bz = bias[oc];
                unsigned int* po = (unsigned int*)outp;
                #pragma unroll
                for (int nf = 0; nf < 4; nf++)
                    #pragma unroll
                    for (int e = 0; e < 2; e++) {
                        int col = wx + nf * 8 + 2 * t + e;
                        float v = g_dep[rowb + col]
                                + bt * (acc[mf][nf][half * 2 + e] + bz);
                        po[rowb + col] = packf(v);
                    }
            } else {
                float scale = bnp[oc] * rsqrtf(bnp[192 + oc] + 1e-5f);
                float off = (bias[oc] - bnp[128 + oc]) * scale + bnp[64 + oc];
                #pragma unroll
                for (int nf = 0; nf < 4; nf++)
                    #pragma unroll
                    for (int e = 0; e < 2; e++) {
                        int col = wx + nf * 8 + 2 * t + e;
                        float v = acc[mf][nf][half * 2 + e];
                        v = fmaxf(fmaf(v, scale, off), 0.0f);
                        if (MODE == 1) ((unsigned int*)outp)[rowb + col] = packf(v);
                        else           ((float*)outp)[rowb + col] = v;
                    }
            }
        }
    }
}

// ---------------------------------------------------------------------------
// map pipeline
// ---------------------------------------------------------------------------
__global__ void upsample_sig_kernel(const float* __restrict__ in_map) {
    int idx = blockIdx.x * blockDim.x + threadIdx.x;
    if (idx >= MAP_ELEMS) return;
    int b = idx / (H2 * W2), p = idx % (H2 * W2);
    int oy = p / W2, ox = p % W2;
    float cy = oy * (63.0f / 127.0f), cx = ox * (63.0f / 127.0f);
    int y0 = (int)floorf(cy); int y1 = min(y0 + 1, HH - 1);
    int x0 = (int)floorf(cx); int x1 = min(x0 + 1, WW - 1);
    float wy = cy - y0, wx = cx - x0;
    const float* m = in_map + b * HH * WW;
    float u = m[y0 * WW + x0] * (1.f - wy) * (1.f - wx) + m[y0 * WW + x1] * (1.f - wy) * wx
            + m[y1 * WW + x0] * wy * (1.f - wx)         + m[y1 * WW + x1] * wy * wx;
    g_im[idx]  = 1.0f / (1.0f + expf(-u));
    g_im1[idx] = 1.0f / (1.0f + expf(-(1.0f - u)));
}

__device__ __forceinline__ float max3x3(const float* m, int oy, int ox) {
    float mx = -3.4e38f;
    #pragma unroll
    for (int dy = -1; dy <= 1; dy++) {
        int y = oy + dy;
        if (y < 0 || y >= H2) continue;
        #pragma unroll
        for (int dx = -1; dx <= 1; dx++) {
            int x = ox + dx;
            if (x < 0 || x >= W2) continue;
            mx = fmaxf(mx, m[y * W2 + x]);
        }
    }
    return mx;
}

__global__ void inc_kernel() {
    int idx = blockIdx.x * blockDim.x + threadIdx.x;
    if (idx >= MAP_ELEMS) return;
    int b = idx / (H2 * W2), p = idx % (H2 * W2);
    const float* m = g_im + b * H2 * W2;
    g_inc[idx] = max3x3(m, p / W2, p % W2) - m[p];
}

__global__ void outmap_kernel() {
    int idx = blockIdx.x * blockDim.x + threadIdx.x;
    if (idx >= MAP_ELEMS) return;
    int b = idx / (H2 * W2), p = idx % (H2 * W2);
    const float* mi = g_inc + b * H2 * W2;
    const float* m1 = g_im1 + b * H2 * W2;
    g_outmap[idx] = max3x3(mi, p / W2, p % W2) + max3x3(m1, p / W2, p % W2) - m1[p];
}

// ---------------------------------------------------------------------------
// out-conv 7x7 (64->1): FFMA2 pixel-pair version.
// Block: 256 threads -> 32x16 px tile. grid (4, 8, 8).
// ---------------------------------------------------------------------------
__global__ __launch_bounds__(256) void out_conv_kernel(
    const float* __restrict__ rin, const float* __restrict__ w,
    const float* __restrict__ bias, float* __restrict__ out)
{
    __shared__ float sIn[22 * 38];
    __shared__ float sW[49];
    int tid = threadIdx.x, tx = tid & 15, ty = tid >> 4;
    int bx = blockIdx.x, by = blockIdx.y, b = blockIdx.z;
    int y0 = by * 16 - 3, x0 = bx * 32 - 3;

    uint64_t acc2 = 0ull;
    for (int ci = 0; ci < C1; ci++) {
        const float* xin = rin + (b * C1 + ci) * H2 * W2;
        for (int i = tid; i < 22 * 38; i += 256) {
            int r = i / 38, c = i % 38, gy = y0 + r, gx = x0 + c;
            sIn[i] = (gy >= 0 && gy < H2 && gx >= 0 && gx < W2) ? xin[gy * W2 + gx] : 0.0f;
        }
        if (tid < 49) sW[tid] = w[ci * 49 + tid];
        __syncthreads();
        #pragma unroll 1
        for (int kh = 0; kh < 7; kh++) {
            float s[8];
            #pragma unroll
            for (int j = 0; j < 4; j++) {
                float2 v2 = *(const float2*)(sIn + (ty + kh) * 38 + 2 * tx + 2 * j);
                s[2 * j] = v2.x;
                s[2 * j + 1] = v2.y;
            }
            #pragma unroll
            for (int kw = 0; kw < 7; kw++) {
                float wv = sW[kh * 7 + kw];
                ffma2(acc2, f2pk(s[kw], s[kw + 1]), f2pk(wv, wv));
            }
        }
        __syncthreads();
    }
    float2 r2 = f2un(acc2);
    int y = by * 16 + ty, xx = bx * 32 + 2 * tx;
    float2 o2;
    o2.x = r2.x + bias[0];
    o2.y = r2.y + bias[0];
    *(float2*)(out + b * H2 * W2 + y * W2 + xx) = o2;
}

// ---------------------------------------------------------------------------
extern "C" void kernel_launch(void* const* d_in, const int* in_sizes, int n_in,
                              void* d_out, int out_size) {
    const float* cur_x   = (const float*)d_in[0];
    const float* dep_x   = (const float*)d_in[1];
    const float* in_map  = (const float*)d_in[2];
    const float* up_w    = (const float*)d_in[3];
    const float* up_b    = (const float*)d_in[4];
    const float* up_bn   = (const float*)d_in[5];
    const float* conv2_w = (const float*)d_in[6];
    const float* conv2_b = (const float*)d_in[7];
    const float* d1_w    = (const float*)d_in[8];
    const float* d1_b    = (const float*)d_in[9];
    const float* d1_bn   = (const float*)d_in[10];
    const float* d2_w    = (const float*)d_in[11];
    const float* d2_b    = (const float*)d_in[12];
    const float* d2_bn   = (const float*)d_in[13];
    const float* d3_w    = (const float*)d_in[14];
    const float* d3_b    = (const float*)d_in[15];
    const float* d3_bn   = (const float*)d_in[16];
    const float* out_w   = (const float*)d_in[17];
    const float* out_b   = (const float*)d_in[18];
    const float* beta    = (const float*)d_in[19];
    float* out = (float*)d_out;

    unsigned int *p_gpk, *p_t1p, *p_r1p, *p_r2p;
    cudaGetSymbolAddress((void**)&p_gpk, g_gpk);
    cudaGetSymbolAddress((void**)&p_t1p, g_t1p);
    cudaGetSymbolAddress((void**)&p_r1p, g_r1p);
    cudaGetSymbolAddress((void**)&p_r2p, g_r2p);

    const int UP_SMEM = 2 * 9216 * 4;   // 73728 B
    cudaFuncSetAttribute(up_mma_kernel, cudaFuncAttributeMaxDynamicSharedMemorySize, UP_SMEM);

    prep_w_kernel<<<(WQ_ELEMS + 255) / 256, 256>>>(up_w);
    prep_w3_all_kernel<<<dim3((W3_ELEMS + 255) / 256, 4), 256>>>(conv2_w, d1_w, d2_w, d3_w);
    pack_dep_t_kernel<<<(XP_ELEMS + 255) / 256, 256>>>(dep_x);

    upsample_sig_kernel<<<MAP_ELEMS / 256, 256>>>(in_map);
    inc_kernel<<<MAP_ELEMS / 256, 256>>>();
    outmap_kernel<<<MAP_ELEMS / 256, 256>>>();
    gate_pack_kernel<<<(R_ELEMS + 255) / 256, 256>>>(cur_x);

    up_mma_kernel<<<dim3(4, 256), 256, UP_SMEM>>>(up_b, up_bn);

    conv3_mma_kernel<0><<<1024, 256>>>(p_gpk, 0, conv2_b, beta, p_t1p);
    conv3_mma_kernel<1><<<1024, 256>>>(p_t1p, 1, d1_b, d1_bn, p_r1p);
    conv3_mma_kernel<1><<<1024, 256>>>(p_r1p, 2, d2_b, d2_bn, p_r2p);
    conv3_mma_kernel<2><<<1024, 256>>>(p_r2p, 3, d3_b, d3_bn, out);

    out_conv_kernel<<<dim3(4, 8, 8), 256>>>(out, out_w, out_b, out + R_ELEMS);
}

// round 17
// speedup vs baseline: 1.1842x; 1.1195x over previous
#include <cuda_runtime.h>
#include <cuda_bf16.h>
#include <math.h>
#include <stdint.h>

#define BB 8
#define C1 64
#define C2 128
#define HH 64
#define WW 64
#define H2 128
#define W2 128

#define R_ELEMS (BB*C1*H2*W2)   /* 8388608 */
#define MAP_ELEMS (BB*H2*W2)    /* 131072  */
#define XP_ELEMS (BB*C2*HH*WW)  /* 2097152 */

__device__ float g_dep[R_ELEMS];
__device__ float g_im[MAP_ELEMS];
__device__ float g_im1[MAP_ELEMS];
__device__ float g_inc[MAP_ELEMS];
__device__ float g_outmap[MAP_ELEMS];

// transposed packed dep_x: [bi][chunk 8][y 64][x 64][16 ci-perm], u32 = hi<<16|lo
__device__ __align__(16) unsigned int g_xt[XP_ELEMS];
// transposed packed tensors for the 3x3 chain: [bi][chunk 4][px 16384][16 ci-perm]
__device__ __align__(16) unsigned int g_gpk[R_ELEMS];   // cur_x * outmap
__device__ __align__(16) unsigned int g_t1p[R_ELEMS];
__device__ __align__(16) unsigned int g_r1p[R_ELEMS];
__device__ __align__(16) unsigned int g_r2p[R_ELEMS];

// transformed up-conv weights: [tap 49][oc 256][ci 128 perm] hi/lo
#define WQ_ELEMS (49 * 256 * 128)
__device__ __align__(16) unsigned short g_wh[WQ_ELEMS];
__device__ __align__(16) unsigned short g_wl[WQ_ELEMS];
// transformed 3x3 weights: 4 slots of [tap 9][oc 64][ci 64 perm] hi/lo
#define W3_ELEMS (9 * 64 * 64)
__device__ __align__(16) unsigned short g_w3h[4 * W3_ELEMS];
__device__ __align__(16) unsigned short g_w3l[4 * W3_ELEMS];

// ---------------- helpers ----------------
__device__ __forceinline__ void split_bf16(float x, unsigned short& h, unsigned short& l) {
    __nv_bfloat16 bh = __float2bfloat16(x);
    float fh = __bfloat162float(bh);
    __nv_bfloat16 bl = __float2bfloat16(x - fh);
    h = *reinterpret_cast<unsigned short*>(&bh);
    l = *reinterpret_cast<unsigned short*>(&bl);
}
__device__ __forceinline__ unsigned int packf(float x) {
    unsigned short h, l;
    split_bf16(x, h, l);
    return ((unsigned int)h << 16) | (unsigned int)l;
}
// perm-slot of ci-within-chunk (inverse of ci = 2*(p>>2)+(p&1)+8*((p>>1)&1))
__device__ __forceinline__ int pperm(int within) {
    int low = within & 7;
    return ((low >> 1) << 2) | ((within >> 3) << 1) | (low & 1);
}
__device__ __forceinline__ void mma16816(float* d,
    uint32_t a0, uint32_t a1, uint32_t a2, uint32_t a3,
    uint32_t b0, uint32_t b1)
{
    asm volatile(
        "mma.sync.aligned.m16n8k16.row.col.f32.bf16.bf16.f32 "
        "{%0,%1,%2,%3}, {%4,%5,%6,%7}, {%8,%9}, {%0,%1,%2,%3};"
        : "+f"(d[0]), "+f"(d[1]), "+f"(d[2]), "+f"(d[3])
        : "r"(a0), "r"(a1), "r"(a2), "r"(a3), "r"(b0), "r"(b1));
}
__device__ __forceinline__ uint32_t prmt(uint32_t a, uint32_t b, uint32_t s) {
    uint32_t r; asm("prmt.b32 %0, %1, %2, %3;" : "=r"(r) : "r"(a), "r"(b), "r"(s)); return r;
}
__device__ __forceinline__ uint32_t smem_u32(const void* p) {
    uint32_t a;
    asm("{ .reg .u64 t; cvta.to.shared.u64 t, %1; cvt.u32.u64 %0, t; }" : "=r"(a) : "l"(p));
    return a;
}
__device__ __forceinline__ void cp_async16(uint32_t saddr, const void* gptr, bool valid) {
    int sz = valid ? 16 : 0;
    asm volatile("cp.async.cg.shared.global [%0], [%1], 16, %2;"
                 :: "r"(saddr), "l"(gptr), "r"(sz) : "memory");
}
__device__ __forceinline__ uint64_t f2pk(float lo, float hi) {
    uint64_t r;
    asm("mov.b64 %0, {%1, %2};" : "=l"(r) : "f"(lo), "f"(hi));
    return r;
}
__device__ __forceinline__ void ffma2(uint64_t& d, uint64_t a, uint64_t b) {
    asm("fma.rn.f32x2 %0, %1, %2, %0;" : "+l"(d) : "l"(a), "l"(b));
}
__device__ __forceinline__ float2 f2un(uint64_t v) {
    float2 r;
    asm("mov.b64 {%0, %1}, %2;" : "=f"(r.x), "=f"(r.y) : "l"(v));
    return r;
}

// ---------------- weight prep ----------------
__global__ void prep_w_kernel(const float* __restrict__ w) {
    int idx = blockIdx.x * blockDim.x + threadIdx.x;
    if (idx >= WQ_ELEMS) return;
    int cix = idx & 127, oc = (idx >> 7) & 255, tap = idx >> 15;
    int p = cix & 15, chunk = cix >> 4;
    int ci = chunk * 16 + 2 * (p >> 2) + (p & 1) + 8 * ((p >> 1) & 1);
    float v = w[(oc * 128 + ci) * 49 + tap];
    unsigned short h, l;
    split_bf16(v, h, l);
    g_wh[idx] = h;
    g_wl[idx] = l;
}
__global__ void prep_w3_all_kernel(const float* __restrict__ w0,
                                   const float* __restrict__ w1,
                                   const float* __restrict__ w2,
                                   const float* __restrict__ w3) {
    int idx = blockIdx.x * blockDim.x + threadIdx.x;
    if (idx >= W3_ELEMS) return;
    int slot = blockIdx.y;
    const float* w = (slot == 0) ? w0 : (slot == 1) ? w1 : (slot == 2) ? w2 : w3;
    int cix = idx & 63, oc = (idx >> 6) & 63, tap = idx >> 12;
    int p = cix & 15, chunk = cix >> 4;
    int ci = chunk * 16 + 2 * (p >> 2) + (p & 1) + 8 * ((p >> 1) & 1);
    float v = w[(oc * 64 + ci) * 9 + tap];
    unsigned short h, l;
    split_bf16(v, h, l);
    g_w3h[slot * W3_ELEMS + idx] = h;
    g_w3l[slot * W3_ELEMS + idx] = l;
}

// ---------------- input pack kernels ----------------
__global__ void pack_dep_t_kernel(const float* __restrict__ x) {
    int i = blockIdx.x * blockDim.x + threadIdx.x;
    if (i >= XP_ELEMS) return;
    int p = i & 15;
    int px = (i >> 4) & 4095;
    int chunk = (i >> 16) & 7;
    int bi = i >> 19;
    int ci = chunk * 16 + 2 * (p >> 2) + (p & 1) + 8 * ((p >> 1) & 1);
    g_xt[i] = packf(x[((bi * C2 + ci) << 12) + px]);
}
// gated pack -> transposed layout [bi][chunk][px][16]
__global__ void gate_pack_kernel(const float* __restrict__ x) {
    int i = blockIdx.x * blockDim.x + threadIdx.x;
    if (i >= R_ELEMS) return;
    int bi = i >> 20;
    int ci = (i >> 14) & 63;
    int px = i & 16383;
    float v = x[i] * g_outmap[(bi << 14) + px];
    int chunk = ci >> 4;
    int p = pperm(ci & 15);
    g_gpk[(((size_t)(bi * 4 + chunk)) << 18) + (px << 4) + p] = packf(v);
}

// ---------------- up-conv via mma.sync bf16x3, cp.async double-buffered ----
__global__ __launch_bounds__(256) void up_mma_kernel(
    const float* __restrict__ bias, const float* __restrict__ bn)
{
    extern __shared__ __align__(16) unsigned int Xs[];   // 2 * 9216

    int tid = threadIdx.x, lane = tid & 31, wid = tid >> 5;
    int g = lane >> 2, t = lane & 3;
    int mblk = blockIdx.x;
    int ntile = blockIdx.y;
    int bi = ntile >> 5;
    int y0 = (ntile & 31) * 2;
    int wm = wid >> 2, wn = wid & 3;
    int wy = wn >> 1;
    int wx = (wn & 1) * 32;
    int ocb = mblk * 64 + wm * 32;

    uint32_t sX = smem_u32(Xs);
    const unsigned int* gxb = g_xt + ((size_t)bi << 19);

    float acc[2][4][4];
    #pragma unroll
    for (int mf = 0; mf < 2; mf++)
        #pragma unroll
        for (int nf = 0; nf < 4; nf++)
            #pragma unroll
            for (int e = 0; e < 4; e++) acc[mf][nf][e] = 0.0f;

    #define UP_PREFETCH(ch, buf) do {                                          \
        const unsigned int* gc = gxb + ((ch) << 16);                           \
        _Pragma("unroll")                                                      \
        for (int i9 = 0; i9 < 9; i9++) {                                       \
            int u = tid + i9 * 256;                                            \
            int pq = u & 3;                                                    \
            int cc = (u >> 2) % 72;                                            \
            int rr = (u >> 2) / 72;                                            \
            int gy = y0 - 3 + rr, gx = cc - 3;                                 \
            bool vv = (gy >= 0 && gy < 64 && gx >= 0 && gx < 64);              \
            const unsigned int* src = gc +                                     \
                (vv ? ((((gy << 6) + gx) << 4) + (pq << 2)) : 0);              \
            cp_async16(sX + (((buf) * 9216 + u * 4) << 2), src, vv);           \
        }                                                                      \
        asm volatile("cp.async.commit_group;" ::: "memory");                   \
    } while (0)

    UP_PREFETCH(0, 0);
    #pragma unroll 1
    for (int chunk = 0; chunk < 8; chunk++) {
        if (chunk + 1 < 8) {
            UP_PREFETCH(chunk + 1, (chunk + 1) & 1);
            asm volatile("cp.async.wait_group 1;" ::: "memory");
        } else {
            asm volatile("cp.async.wait_group 0;" ::: "memory");
        }
        __syncthreads();
        const unsigned int* Xb = Xs + (chunk & 1) * 9216;

        for (int kh = 0; kh < 7; kh++) {
            #pragma unroll
            for (int kw = 0; kw < 7; kw++) {
                int tap = kh * 7 + kw;
                size_t aoff = ((size_t)(tap * 256 + ocb + g) << 7) + chunk * 16 + t * 4;
                uint2 ah00 = *(const uint2*)(g_wh + aoff);
                uint2 ah01 = *(const uint2*)(g_wh + aoff + (8 << 7));
                uint2 ah10 = *(const uint2*)(g_wh + aoff + (16 << 7));
                uint2 ah11 = *(const uint2*)(g_wh + aoff + (24 << 7));
                uint2 al00 = *(const uint2*)(g_wl + aoff);
                uint2 al01 = *(const uint2*)(g_wl + aoff + (8 << 7));
                uint2 al10 = *(const uint2*)(g_wl + aoff + (16 << 7));
                uint2 al11 = *(const uint2*)(g_wl + aoff + (24 << 7));
                int brow = wy + kh;
                int bcol = wx + kw + g;
                #pragma unroll
                for (int nf = 0; nf < 4; nf++) {
                    int spos = (brow * 72 + bcol + nf * 8) * 16 + t * 4;
                    uint4 q = *(const uint4*)(Xb + spos);
                    uint2 bh, bl;
                    bh.x = prmt(q.x, q.y, 0x7632);
                    bh.y = prmt(q.z, q.w, 0x7632);
                    bl.x = prmt(q.x, q.y, 0x5410);
                    bl.y = prmt(q.z, q.w, 0x5410);
                    mma16816(acc[0][nf], ah00.x, ah01.x, ah00.y, ah01.y, bh.x, bh.y);
                    mma16816(acc[1][nf], ah10.x, ah11.x, ah10.y, ah11.y, bh.x, bh.y);
                    mma16816(acc[0][nf], al00.x, al01.x, al00.y, al01.y, bh.x, bh.y);
                    mma16816(acc[1][nf], al10.x, al11.x, al10.y, al11.y, bh.x, bh.y);
                    mma16816(acc[0][nf], ah00.x, ah01.x, ah00.y, ah01.y, bl.x, bl.y);
                    mma16816(acc[1][nf], ah10.x, ah11.x, ah10.y, ah11.y, bl.x, bl.y);
                }
            }
        }
        __syncthreads();
    }

    int yy = y0 + wy;
    #pragma unroll
    for (int mf = 0; mf < 2; mf++) {
        #pragma unroll
        for (int half = 0; half < 2; half++) {
            int oc = ocb + mf * 16 + g + half * 8;
            float scale = bn[oc] * rsqrtf(bn[768 + oc] + 1e-5f);
            float off = (bias[oc] - bn[512 + oc]) * scale + bn[256 + oc];
            int c = oc >> 2, a = (oc >> 1) & 1, d = oc & 1;
            size_t rowb = ((size_t)(bi * C1 + c) * H2 + 2 * yy + a) * W2 + d;
            #pragma unroll
            for (int nf = 0; nf < 4; nf++) {
                #pragma unroll
                for (int e = 0; e < 2; e++) {
                    float v = acc[mf][nf][half * 2 + e];
                    int col = wx + nf * 8 + 2 * t + e;
                    g_dep[rowb + 2 * col] = fmaxf(fmaf(v, scale, off), 0.0f);
                }
            }
        }
    }
}

// ---------------- 3x3 convs via mma.sync bf16x3, transposed in, cp.async ----
// CTA: 64 oc x 128 px (one image row). grid = 1024 (bi*128 + y0).
// in: transposed packed [bi][chunk 4][px][16]. X tile 3x132x16 u32, dbl-buffered.
// MODE 0: t1 = dep + beta*(acc+bias) -> transposed packed out
// MODE 1: BN+ReLU -> transposed packed out
// MODE 2: BN+ReLU -> fp32 planar out
template<int MODE>
__global__ __launch_bounds__(256) void conv3_mma_kernel(
    const unsigned int* __restrict__ in, int wslot,
    const float* __restrict__ bias, const float* __restrict__ bnp,
    void* __restrict__ outp)
{
    extern __shared__ __align__(16) unsigned int Xs[];   // 2 * 6336

    int tid = threadIdx.x, lane = tid & 31, wid = tid >> 5;
    int g = lane >> 2, t = lane & 3;
    int blk = blockIdx.x;
    int bi = blk >> 7;
    int y0 = blk & 127;
    int wm = wid >> 2, wn = wid & 3;
    int wx = wn * 32;
    int ocb = wm * 32;

    uint32_t sX = smem_u32(Xs);
    const unsigned short* wh = g_w3h + wslot * W3_ELEMS;
    const unsigned short* wl = g_w3l + wslot * W3_ELEMS;

    float acc[2][4][4];
    #pragma unroll
    for (int mf = 0; mf < 2; mf++)
        #pragma unroll
        for (int nf = 0; nf < 4; nf++)
            #pragma unroll
            for (int e = 0; e < 4; e++) acc[mf][nf][e] = 0.0f;

    #define C3_PREFETCH(ch, buf) do {                                          \
        const unsigned int* gc = in + ((size_t)(bi * 4 + (ch)) << 18);         \
        _Pragma("unroll")                                                      \
        for (int i7 = 0; i7 < 7; i7++) {                                       \
            int u = tid + i7 * 256;                                            \
            if (u < 1584) {                                                    \
                int pq = u & 3;                                                \
                int cell = u >> 2;                                             \
                int cc = cell % 132;                                           \
                int rr = cell / 132;                                           \
                int gy = y0 - 1 + rr, gx = cc - 1;                             \
                bool vv = (gy >= 0 && gy < H2 && gx >= 0 && gx < W2);          \
                const unsigned int* src = gc +                                 \
                    (vv ? ((((gy << 7) + gx) << 4) + (pq << 2)) : 0);          \
                cp_async16(sX + (((buf) * 6336 + u * 4) << 2), src, vv);       \
            }                                                                  \
        }                                                                      \
        asm volatile("cp.async.commit_group;" ::: "memory");                   \
    } while (0)

    C3_PREFETCH(0, 0);
    #pragma unroll 1
    for (int chunk = 0; chunk < 4; chunk++) {
        if (chunk + 1 < 4) {
            C3_PREFETCH(chunk + 1, (chunk + 1) & 1);
            asm volatile("cp.async.wait_group 1;" ::: "memory");
        } else {
            asm volatile("cp.async.wait_group 0;" ::: "memory");
        }
        __syncthreads();
        const unsigned int* Xb = Xs + (chunk & 1) * 6336;

        #pragma unroll
        for (int kh = 0; kh < 3; kh++) {
            #pragma unroll
            for (int kw = 0; kw < 3; kw++) {
                int tap = kh * 3 + kw;
                int aoff = ((tap * 64 + ocb + g) << 6) + chunk * 16 + t * 4;
                uint2 ah00 = *(const uint2*)(wh + aoff);
                uint2 ah01 = *(const uint2*)(wh + aoff + (8 << 6));
                uint2 ah10 = *(const uint2*)(wh + aoff + (16 << 6));
                uint2 ah11 = *(const uint2*)(wh + aoff + (24 << 6));
                uint2 al00 = *(const uint2*)(wl + aoff);
                uint2 al01 = *(const uint2*)(wl + aoff + (8 << 6));
                uint2 al10 = *(const uint2*)(wl + aoff + (16 << 6));
                uint2 al11 = *(const uint2*)(wl + aoff + (24 << 6));
                int bcol = wx + kw + g;
                #pragma unroll
                for (int nf = 0; nf < 4; nf++) {
                    int spos = ((kh * 132 + bcol + nf * 8) << 4) + t * 4;
                    uint4 q = *(const uint4*)(Xb + spos);
                    uint2 bh, bl;
                    bh.x = prmt(q.x, q.y, 0x7632);
                    bh.y = prmt(q.z, q.w, 0x7632);
                    bl.x = prmt(q.x, q.y, 0x5410);
                    bl.y = prmt(q.z, q.w, 0x5410);
                    mma16816(acc[0][nf], ah00.x, ah01.x, ah00.y, ah01.y, bh.x, bh.y);
                    mma16816(acc[1][nf], ah10.x, ah11.x, ah10.y, ah11.y, bh.x, bh.y);
                    mma16816(acc[0][nf], al00.x, al01.x, al00.y, al01.y, bh.x, bh.y);
                    mma16816(acc[1][nf], al10.x, al11.x, al10.y, al11.y, bh.x, bh.y);
                    mma16816(acc[0][nf], ah00.x, ah01.x, ah00.y, ah01.y, bl.x, bl.y);
                    mma16816(acc[1][nf], ah10.x, ah11.x, ah10.y, ah11.y, bl.x, bl.y);
                }
            }
        }
        __syncthreads();
    }

    #pragma unroll
    for (int mf = 0; mf < 2; mf++) {
        #pragma unroll
        for (int half = 0; half < 2; half++) {
            int oc = ocb + mf * 16 + g + half * 8;
            if (MODE == 2) {
                float scale = bnp[oc] * rsqrtf(bnp[192 + oc] + 1e-5f);
                float off = (bias[oc] - bnp[128 + oc]) * scale + bnp[64 + oc];
                size_t rowb = ((size_t)(bi * C1 + oc) << 14) + (y0 << 7);
                #pragma unroll
                for (int nf = 0; nf < 4; nf++)
                    #pragma unroll
                    for (int e = 0; e < 2; e++) {
                        int col = wx + nf * 8 + 2 * t + e;
                        float v = acc[mf][nf][half * 2 + e];
                        ((float*)outp)[rowb + col] = fmaxf(fmaf(v, scale, off), 0.0f);
                    }
            } else {
                // transposed packed out: [bi][chunk][px][16]
                int och = oc >> 4;
                int p = pperm(oc & 15);
                size_t tb = (((size_t)(bi * 4 + och)) << 18) + ((size_t)(y0 << 7) << 4) + p;
                unsigned int* po = (unsigned int*)outp;
                if (MODE == 0) {
                    float bt = bnp[0];
                    float bz = bias[oc];
                    size_t rowb = ((size_t)(bi * C1 + oc) << 14) + (y0 << 7);
                    #pragma unroll
                    for (int nf = 0; nf < 4; nf++)
                        #pragma unroll
                        for (int e = 0; e < 2; e++) {
                            int col = wx + nf * 8 + 2 * t + e;
                            float v = g_dep[rowb + col]
                                    + bt * (acc[mf][nf][half * 2 + e] + bz);
                            po[tb + ((size_t)col << 4)] = packf(v);
                        }
                } else {
                    float scale = bnp[oc] * rsqrtf(bnp[192 + oc] + 1e-5f);
                    float off = (bias[oc] - bnp[128 + oc]) * scale + bnp[64 + oc];
                    #pragma unroll
                    for (int nf = 0; nf < 4; nf++)
                        #pragma unroll
                        for (int e = 0; e < 2; e++) {
                            int col = wx + nf * 8 + 2 * t + e;
                            float v = acc[mf][nf][half * 2 + e];
                            v = fmaxf(fmaf(v, scale, off), 0.0f);
                            po[tb + ((size_t)col << 4)] = packf(v);
                        }
                }
            }
        }
    }
}

// ---------------------------------------------------------------------------
// map pipeline
// ---------------------------------------------------------------------------
__global__ void upsample_sig_kernel(const float* __restrict__ in_map) {
    int idx = blockIdx.x * blockDim.x + threadIdx.x;
    if (idx >= MAP_ELEMS) return;
    int b = idx / (H2 * W2), p = idx % (H2 * W2);
    int oy = p / W2, ox = p % W2;
    float cy = oy * (63.0f / 127.0f), cx = ox * (63.0f / 127.0f);
    int y0 = (int)floorf(cy); int y1 = min(y0 + 1, HH - 1);
    int x0 = (int)floorf(cx); int x1 = min(x0 + 1, WW - 1);
    float wy = cy - y0, wx = cx - x0;
    const float* m = in_map + b * HH * WW;
    float u = m[y0 * WW + x0] * (1.f - wy) * (1.f - wx) + m[y0 * WW + x1] * (1.f - wy) * wx
            + m[y1 * WW + x0] * wy * (1.f - wx)         + m[y1 * WW + x1] * wy * wx;
    g_im[idx]  = 1.0f / (1.0f + expf(-u));
    g_im1[idx] = 1.0f / (1.0f + expf(-(1.0f - u)));
}

__device__ __forceinline__ float max3x3(const float* m, int oy, int ox) {
    float mx = -3.4e38f;
    #pragma unroll
    for (int dy = -1; dy <= 1; dy++) {
        int y = oy + dy;
        if (y < 0 || y >= H2) continue;
        #pragma unroll
        for (int dx = -1; dx <= 1; dx++) {
            int x = ox + dx;
            if (x < 0 || x >= W2) continue;
            mx = fmaxf(mx, m[y * W2 + x]);
        }
    }
    return mx;
}

__global__ void inc_kernel() {
    int idx = blockIdx.x * blockDim.x + threadIdx.x;
    if (idx >= MAP_ELEMS) return;
    int b = idx / (H2 * W2), p = idx % (H2 * W2);
    const float* m = g_im + b * H2 * W2;
    g_inc[idx] = max3x3(m, p / W2, p % W2) - m[p];
}

__global__ void outmap_kernel() {
    int idx = blockIdx.x * blockDim.x + threadIdx.x;
    if (idx >= MAP_ELEMS) return;
    int b = idx / (H2 * W2), p = idx % (H2 * W2);
    const float* mi = g_inc + b * H2 * W2;
    const float* m1 = g_im1 + b * H2 * W2;
    g_outmap[idx] = max3x3(mi, p / W2, p % W2) + max3x3(m1, p / W2, p % W2) - m1[p];
}

// ---------------------------------------------------------------------------
// out-conv 7x7 (64->1): FFMA2 pixel-pair version.
// ---------------------------------------------------------------------------
__global__ __launch_bounds__(256) void out_conv_kernel(
    const float* __restrict__ rin, const float* __restrict__ w,
    const float* __restrict__ bias, float* __restrict__ out)
{
    __shared__ float sIn[22 * 38];
    __shared__ float sW[49];
    int tid = threadIdx.x, tx = tid & 15, ty = tid >> 4;
    int bx = blockIdx.x, by = blockIdx.y, b = blockIdx.z;
    int y0 = by * 16 - 3, x0 = bx * 32 - 3;

    uint64_t acc2 = 0ull;
    for (int ci = 0; ci < C1; ci++) {
        const float* xin = rin + (b * C1 + ci) * H2 * W2;
        for (int i = tid; i < 22 * 38; i += 256) {
            int r = i / 38, c = i % 38, gy = y0 + r, gx = x0 + c;
            sIn[i] = (gy >= 0 && gy < H2 && gx >= 0 && gx < W2) ? xin[gy * W2 + gx] : 0.0f;
        }
        if (tid < 49) sW[tid] = w[ci * 49 + tid];
        __syncthreads();
        #pragma unroll 1
        for (int kh = 0; kh < 7; kh++) {
            float s[8];
            #pragma unroll
            for (int j = 0; j < 4; j++) {
                float2 v2 = *(const float2*)(sIn + (ty + kh) * 38 + 2 * tx + 2 * j);
                s[2 * j] = v2.x;
                s[2 * j + 1] = v2.y;
            }
            #pragma unroll
            for (int kw = 0; kw < 7; kw++) {
                float wv = sW[kh * 7 + kw];
                ffma2(acc2, f2pk(s[kw], s[kw + 1]), f2pk(wv, wv));
            }
        }
        __syncthreads();
    }
    float2 r2 = f2un(acc2);
    int y = by * 16 + ty, xx = bx * 32 + 2 * tx;
    float2 o2;
    o2.x = r2.x + bias[0];
    o2.y = r2.y + bias[0];
    *(float2*)(out + b * H2 * W2 + y * W2 + xx) = o2;
}

// ---------------------------------------------------------------------------
extern "C" void kernel_launch(void* const* d_in, const int* in_sizes, int n_in,
                              void* d_out, int out_size) {
    const float* cur_x   = (const float*)d_in[0];
    const float* dep_x   = (const float*)d_in[1];
    const float* in_map  = (const float*)d_in[2];
    const float* up_w    = (const float*)d_in[3];
    const float* up_b    = (const float*)d_in[4];
    const float* up_bn   = (const float*)d_in[5];
    const float* conv2_w = (const float*)d_in[6];
    const float* conv2_b = (const float*)d_in[7];
    const float* d1_w    = (const float*)d_in[8];
    const float* d1_b    = (const float*)d_in[9];
    const float* d1_bn   = (const float*)d_in[10];
    const float* d2_w    = (const float*)d_in[11];
    const float* d2_b    = (const float*)d_in[12];
    const float* d2_bn   = (const float*)d_in[13];
    const float* d3_w    = (const float*)d_in[14];
    const float* d3_b    = (const float*)d_in[15];
    const float* d3_bn   = (const float*)d_in[16];
    const float* out_w   = (const float*)d_in[17];
    const float* out_b   = (const float*)d_in[18];
    const float* beta    = (const float*)d_in[19];
    float* out = (float*)d_out;

    unsigned int *p_gpk, *p_t1p, *p_r1p, *p_r2p;
    cudaGetSymbolAddress((void**)&p_gpk, g_gpk);
    cudaGetSymbolAddress((void**)&p_t1p, g_t1p);
    cudaGetSymbolAddress((void**)&p_r1p, g_r1p);
    cudaGetSymbolAddress((void**)&p_r2p, g_r2p);

    const int UP_SMEM = 2 * 9216 * 4;   // 73728 B
    const int C3_SMEM = 2 * 6336 * 4;   // 50688 B
    cudaFuncSetAttribute(up_mma_kernel, cudaFuncAttributeMaxDynamicSharedMemorySize, UP_SMEM);
    cudaFuncSetAttribute(conv3_mma_kernel<0>, cudaFuncAttributeMaxDynamicSharedMemorySize, C3_SMEM);
    cudaFuncSetAttribute(conv3_mma_kernel<1>, cudaFuncAttributeMaxDynamicSharedMemorySize, C3_SMEM);
    cudaFuncSetAttribute(conv3_mma_kernel<2>, cudaFuncAttributeMaxDynamicSharedMemorySize, C3_SMEM);

    prep_w_kernel<<<(WQ_ELEMS + 255) / 256, 256>>>(up_w);
    prep_w3_all_kernel<<<dim3((W3_ELEMS + 255) / 256, 4), 256>>>(conv2_w, d1_w, d2_w, d3_w);
    pack_dep_t_kernel<<<(XP_ELEMS + 255) / 256, 256>>>(dep_x);

    upsample_sig_kernel<<<MAP_ELEMS / 256, 256>>>(in_map);
    inc_kernel<<<MAP_ELEMS / 256, 256>>>();
    outmap_kernel<<<MAP_ELEMS / 256, 256>>>();
    gate_pack_kernel<<<(R_ELEMS + 255) / 256, 256>>>(cur_x);

    up_mma_kernel<<<dim3(4, 256), 256, UP_SMEM>>>(up_b, up_bn);

    conv3_mma_kernel<0><<<1024, 256, C3_SMEM>>>(p_gpk, 0, conv2_b, beta, p_t1p);
    conv3_mma_kernel<1><<<1024, 256, C3_SMEM>>>(p_t1p, 1, d1_b, d1_bn, p_r1p);
    conv3_mma_kernel<1><<<1024, 256, C3_SMEM>>>(p_r1p, 2, d2_b, d2_bn, p_r2p);
    conv3_mma_kernel<2><<<1024, 256, C3_SMEM>>>(p_r2p, 3, d3_b, d3_bn, out);

    out_conv_kernel<<<dim3(4, 8, 8), 256>>>(out, out_w, out_b, out + R_ELEMS);
}